// round 3
// baseline (speedup 1.0000x reference)
#include <cuda_runtime.h>
#include <cuda_fp16.h>
#include <math.h>

#define B_    32
#define IC    2048
#define OC    64
#define OD    32
#define ID    16
#define ITERS 5
#define OCD   (OC*OD)   // 2048
#define NSLOT 128       // partial slots per batch

// Scratch (static device globals; no allocation at launch time).
// u_hat layout: [b][i][d][o]  (p = d*64 + o), fp16  -> 256 MB
__device__ __align__(16) __half g_uhat[(size_t)B_ * IC * OCD];
// partial s:   [b][slot][d][o], fp16               -> 16 MB
__device__ __align__(16) __half g_spart[(size_t)B_ * NSLOT * OCD];
// V = sum of v over past iters: [b][d][o], fp32
__device__ float g_V[B_ * OCD];

__global__ void init_V() {
    int idx = blockIdx.x * blockDim.x + threadIdx.x;
    if (idx < B_ * OCD) g_V[idx] = 0.f;
}

__device__ __forceinline__ float dot16(const float4* w, const float* xb) {
    float4 w0 = w[0], w1 = w[1], w2 = w[2], w3 = w[3];
    float u = w0.x * xb[0];
    u = fmaf(w0.y, xb[1], u);  u = fmaf(w0.z, xb[2], u);  u = fmaf(w0.w, xb[3], u);
    u = fmaf(w1.x, xb[4], u);  u = fmaf(w1.y, xb[5], u);  u = fmaf(w1.z, xb[6], u);
    u = fmaf(w1.w, xb[7], u);  u = fmaf(w2.x, xb[8], u);  u = fmaf(w2.y, xb[9], u);
    u = fmaf(w2.z, xb[10], u); u = fmaf(w2.w, xb[11], u); u = fmaf(w3.x, xb[12], u);
    u = fmaf(w3.y, xb[13], u); u = fmaf(w3.z, xb[14], u); u = fmaf(w3.w, xb[15], u);
    return u;
}

// Pass A: u_hat[b,i,d,o] = sum_k W[i,o,d,k] * x[b,i,k], stored fp16.
// One CTA per i. Thread handles pairs (p, p+1) = (d, o) and (d, o+1); half2 store.
__global__ __launch_bounds__(256) void uhat_kernel(const float* __restrict__ x,
                                                   const float* __restrict__ W) {
    int i = blockIdx.x;
    int t = threadIdx.x;
    __shared__ float xs[B_][ID];
    for (int idx = t; idx < B_ * ID; idx += 256) {
        int b = idx >> 4, k = idx & 15;
        xs[b][k] = x[((size_t)b * IC + i) * ID + k];
    }
    __syncthreads();

#pragma unroll
    for (int j = 0; j < 4; j++) {
        int p = 512 * j + 2 * t;           // even; pair (p, p+1): same d, adjacent o
        int d = p >> 6;
        int o = p & 63;
        const float4* w0 = (const float4*)(W + ((size_t)i * OCD + (size_t)o * OD + d) * ID);
        const float4* w1 = (const float4*)(W + ((size_t)i * OCD + (size_t)(o + 1) * OD + d) * ID);
        float4 a0 = w0[0], a1 = w0[1], a2 = w0[2], a3 = w0[3];
        float4 b0 = w1[0], b1 = w1[1], b2 = w1[2], b3 = w1[3];
        float4 A[4] = {a0, a1, a2, a3};
        float4 Bv[4] = {b0, b1, b2, b3};
        for (int b = 0; b < B_; b++) {
            const float* xb = xs[b];
            float u0 = dot16(A, xb);
            float u1 = dot16(Bv, xb);
            __half2* dst = (__half2*)(g_uhat + ((size_t)b * IC + i) * OCD + p);
            *dst = __floats2half2_rn(u0, u1);
        }
    }
}

// Routing pass. Grid (16 chunks, 32 b), 256 thr, 8 warps.
// Warp w handles 16 i's (i = chunk*128 + ii*8 + w); lane = d.
// Per i: load 64 halves (8x LDG.128), softmax over o of u*V, acc[o] += c*u (fp32).
// Warp writes its fp16 partial to slot = chunk*8 + w.
__global__ __launch_bounds__(256, 2) void routing_kernel() {
    int chunk = blockIdx.x;
    int b = blockIdx.y;
    int t = threadIdx.x;
    int w = t >> 5, d = t & 31;

    __shared__ float   Vsf[32 * 66];    // padded rows: conflict-free float2 LDS
    __shared__ __half2 Vsh[32 * 33];    // padded rows: conflict-free half2 LDS
    for (int idx = t; idx < 1024; idx += 256) {
        int dd = idx >> 5, op = idx & 31;
        float2 vv = ((const float2*)(g_V + b * OCD + dd * 64))[op];
        Vsf[dd * 66 + 2 * op]     = vv.x;
        Vsf[dd * 66 + 2 * op + 1] = vv.y;
        Vsh[dd * 33 + op] = __floats2half2_rn(vv.x, vv.y);
    }
    __syncthreads();

    float acc[OC];
#pragma unroll
    for (int o = 0; o < OC; o++) acc[o] = 0.f;

    for (int ii = 0; ii < 16; ii++) {
        int i = chunk * 128 + ii * 8 + w;
        const uint4* up = (const uint4*)(g_uhat + ((size_t)b * IC + i) * OCD);
        uint4 U[8];
#pragma unroll
        for (int k = 0; k < 8; k++) U[k] = up[d * 8 + k];   // 64 halves: this lane's o-row

        // max pass (half2; approximate max is fine for stability)
        __half2 mh = __float2half2_rn(-60000.f);
#pragma unroll
        for (int op = 0; op < 32; op++) {
            __half2 uh = ((__half2*)U)[op];
            mh = __hmax2(mh, __hmul2(uh, Vsh[d * 33 + op]));
        }
        float2 mf = __half22float2(mh);
        float m = fmaxf(mf.x, mf.y);

        // exp pass (fp32 logits); stash e*u back into U as half2
        float Z = 0.f;
#pragma unroll
        for (int op = 0; op < 32; op++) {
            float2 uf = __half22float2(((__half2*)U)[op]);
            float2 vf = *(const float2*)&Vsf[d * 66 + 2 * op];
            float e0 = __expf(fmaf(uf.x, vf.x, -m));
            float e1 = __expf(fmaf(uf.y, vf.y, -m));
            Z += e0 + e1;
            ((__half2*)U)[op] = __floats2half2_rn(uf.x * e0, uf.y * e1);
        }
        float rZ = 1.0f / Z;
#pragma unroll
        for (int op = 0; op < 32; op++) {
            float2 tf = __half22float2(((__half2*)U)[op]);
            acc[2 * op]     = fmaf(tf.x, rZ, acc[2 * op]);
            acc[2 * op + 1] = fmaf(tf.y, rZ, acc[2 * op + 1]);
        }
    }

    int slot = chunk * 8 + w;
    __half2* sp = (__half2*)(g_spart + ((size_t)b * NSLOT + slot) * OCD + d * 64);
#pragma unroll
    for (int op = 0; op < 32; op++)
        sp[op] = __floats2half2_rn(acc[2 * op], acc[2 * op + 1]);
}

// Reduce 128 fp16 slots, squash over d, update V (and write out on last iter).
// Grid = 32 (b), 256 threads; thread t owns p = 8t..8t+7 (same d, 8 consecutive o).
__global__ __launch_bounds__(256) void update_kernel(float* __restrict__ out, int is_last) {
    int b = blockIdx.x;
    int t = threadIdx.x;

    float s[8] = {0.f, 0.f, 0.f, 0.f, 0.f, 0.f, 0.f, 0.f};
    for (int slot = 0; slot < NSLOT; slot++) {
        const uint4* sp = (const uint4*)(g_spart + ((size_t)b * NSLOT + slot) * OCD);
        uint4 raw = sp[t];
#pragma unroll
        for (int jj = 0; jj < 4; jj++) {
            float2 f = __half22float2(((__half2*)&raw)[jj]);
            s[2 * jj]     += f.x;
            s[2 * jj + 1] += f.y;
        }
    }

    int d = t >> 3, o0 = (t & 7) * 8;
    __shared__ float sq[OD][OC];   // 8 KB
#pragma unroll
    for (int k = 0; k < 8; k++) {
        float sum8 = s[k];
        sq[d][o0 + k] = sum8 * sum8;
    }
    __syncthreads();

    __shared__ float n2s[OC];
    if (t < OC) {
        float n2 = 0.f;
#pragma unroll
        for (int dd = 0; dd < OD; dd++) n2 += sq[dd][t];
        n2s[t] = n2;
    }
    __syncthreads();

#pragma unroll
    for (int k = 0; k < 8; k++) {
        int o = o0 + k;
        float n2 = n2s[o];
        float factor = n2 / ((1.f + n2) * sqrtf(n2 + 1e-8f));
        float v = factor * s[k];
        int p = t * 8 + k;                 // = d*64 + o
        g_V[b * OCD + p] += v;
        if (is_last) out[((size_t)b * OC + o) * OD + d] = v;
    }
}

extern "C" void kernel_launch(void* const* d_in, const int* in_sizes, int n_in,
                              void* d_out, int out_size) {
    const float* x = (const float*)d_in[0];
    const float* W = (const float*)d_in[1];
    if (n_in >= 2 && in_sizes[0] > in_sizes[1]) {  // defensive: x is the smaller input
        const float* tmp = x; x = W; W = tmp;
    }
    float* out = (float*)d_out;

    init_V<<<(B_ * OCD + 255) / 256, 256>>>();
    uhat_kernel<<<IC, 256>>>(x, W);
    for (int r = 0; r < ITERS; r++) {
        routing_kernel<<<dim3(16, B_), 256>>>();
        update_kernel<<<B_, 256>>>(out, r == ITERS - 1);
    }
}

// round 4
// speedup vs baseline: 1.5011x; 1.5011x over previous
#include <cuda_runtime.h>
#include <cuda_fp16.h>
#include <math.h>

#define B_    32
#define IC    2048
#define OC    64
#define OD    32
#define ID    16
#define ITERS 5
#define OCD   (OC*OD)   // 2048
#define NSLOT 128

// Scratch (static device globals; no allocation at launch time).
__device__ __align__(16) __half g_uhat[(size_t)B_ * IC * OCD];   // [b][i][o][d] fp16, 256 MB
__device__ float g_spart[(size_t)B_ * NSLOT * OCD];              // [b][slot][o*32+d] fp32, 32 MB
__device__ float g_V[B_ * OCD];                                  // [b][o*32+d]

__global__ void init_V() {
    int idx = blockIdx.x * blockDim.x + threadIdx.x;
    if (idx < B_ * OCD) g_V[idx] = 0.f;
}

// ---- packed f32x2 helpers (Blackwell FFMA2; ptxas won't emit from C++) ----
__device__ __forceinline__ unsigned long long pk2(float a, float b) {
    unsigned long long r;
    asm("mov.b64 %0, {%1, %2};" : "=l"(r) : "f"(a), "f"(b));
    return r;
}
__device__ __forceinline__ unsigned long long fma2(unsigned long long a,
                                                   unsigned long long b,
                                                   unsigned long long c) {
    unsigned long long r;
    asm("fma.rn.f32x2 %0, %1, %2, %3;" : "=l"(r) : "l"(a), "l"(b), "l"(c));
    return r;
}
__device__ __forceinline__ float2 unpk2(unsigned long long v) {
    float2 f;
    asm("mov.b64 {%0, %1}, %2;" : "=f"(f.x), "=f"(f.y) : "l"(v));
    return f;
}

// Pass A: u_hat[b,i,o,d] = sum_k W[i,o,d,k] * x[b,i,k], fp16 store.
// One CTA per i. Thread handles rows p0 = t+512j and p1 = p0+256 (p = o*32+d);
// consecutive threads -> consecutive W rows (coalesced) and consecutive stores.
// The two rows' dots are computed together with packed f32x2 FMAs.
__global__ __launch_bounds__(256) void uhat_kernel(const float* __restrict__ x,
                                                   const float* __restrict__ W) {
    int i = blockIdx.x;
    int t = threadIdx.x;
    __shared__ unsigned long long xs2[B_][ID];   // pre-packed (xk, xk)
    for (int idx = t; idx < B_ * ID; idx += 256) {
        int b = idx >> 4, k = idx & 15;
        float xv = x[((size_t)b * IC + i) * ID + k];
        xs2[b][k] = pk2(xv, xv);
    }
    __syncthreads();

#pragma unroll
    for (int j = 0; j < 4; j++) {
        int p0 = t + 512 * j;
        int p1 = p0 + 256;
        const float4* w0p = (const float4*)(W + ((size_t)i * OCD + p0) * ID);
        const float4* w1p = (const float4*)(W + ((size_t)i * OCD + p1) * ID);
        float4 a0 = w0p[0], a1 = w0p[1], a2 = w0p[2], a3 = w0p[3];
        float4 b0 = w1p[0], b1 = w1p[1], b2 = w1p[2], b3 = w1p[3];
        // packed pairs (w_p0[k], w_p1[k])
        unsigned long long wp[ID];
        wp[0]  = pk2(a0.x, b0.x); wp[1]  = pk2(a0.y, b0.y);
        wp[2]  = pk2(a0.z, b0.z); wp[3]  = pk2(a0.w, b0.w);
        wp[4]  = pk2(a1.x, b1.x); wp[5]  = pk2(a1.y, b1.y);
        wp[6]  = pk2(a1.z, b1.z); wp[7]  = pk2(a1.w, b1.w);
        wp[8]  = pk2(a2.x, b2.x); wp[9]  = pk2(a2.y, b2.y);
        wp[10] = pk2(a2.z, b2.z); wp[11] = pk2(a2.w, b2.w);
        wp[12] = pk2(a3.x, b3.x); wp[13] = pk2(a3.y, b3.y);
        wp[14] = pk2(a3.z, b3.z); wp[15] = pk2(a3.w, b3.w);

        for (int b = 0; b < B_; b++) {
            unsigned long long acc = pk2(0.f, 0.f);
#pragma unroll
            for (int k = 0; k < ID; k++)
                acc = fma2(wp[k], xs2[b][k], acc);
            float2 u = unpk2(acc);
            size_t base = ((size_t)b * IC + i) * OCD;
            g_uhat[base + p0] = __float2half_rn(u.x);
            g_uhat[base + p1] = __float2half_rn(u.y);
        }
    }
}

// Routing pass (R1-proven structure). Grid (16, 32). Warp w: 16 i's, lane = d.
__global__ __launch_bounds__(256) void routing_kernel() {
    int chunk = blockIdx.x;
    int b = blockIdx.y;
    int t = threadIdx.x;
    __shared__ float Vs[OCD];
    for (int idx = t; idx < OCD; idx += 256) Vs[idx] = g_V[b * OCD + idx];
    __syncthreads();

    int w = t >> 5, d = t & 31;
    float acc[OC];
#pragma unroll
    for (int o = 0; o < OC; o++) acc[o] = 0.f;

    for (int ii = 0; ii < 16; ii++) {
        int i = chunk * 128 + ii * 8 + w;
        const __half* up = g_uhat + ((size_t)b * IC + i) * OCD + d;
        float u[OC];
#pragma unroll
        for (int o = 0; o < OC; o++) u[o] = __half2float(up[o * OD]);  // 64B coalesced per o

        float m = -1e30f;
#pragma unroll
        for (int o = 0; o < OC; o++) m = fmaxf(m, u[o] * Vs[o * OD + d]);

        float Z = 0.f;
#pragma unroll
        for (int o = 0; o < OC; o++) {
            float e = __expf(fmaf(u[o], Vs[o * OD + d], -m));
            Z += e;
            u[o] *= e;
        }
        float rZ = 1.0f / Z;
#pragma unroll
        for (int o = 0; o < OC; o++) acc[o] = fmaf(u[o], rZ, acc[o]);
    }

    int slot = chunk * 8 + w;  // 0..127
    float* sp = g_spart + ((size_t)b * NSLOT + slot) * OCD + d;
#pragma unroll
    for (int o = 0; o < OC; o++) sp[o * OD] = acc[o];
}

// Reduce 128 fp32 slots, squash over d, update V (+ output on last iter).
__global__ __launch_bounds__(256) void update_kernel(float* __restrict__ out, int is_last) {
    int bo = blockIdx.x;       // 0..2047
    int b = bo >> 6, o = bo & 63;
    int t = threadIdx.x;
    int g = t >> 5, d = t & 31;

    float s = 0.f;
    for (int c = g; c < NSLOT; c += 8)
        s += g_spart[((size_t)b * NSLOT + c) * OCD + o * OD + d];

    __shared__ float red[8][OD];
    red[g][d] = s;
    __syncthreads();

    if (t < 32) {
        float tot = 0.f;
#pragma unroll
        for (int gg = 0; gg < 8; gg++) tot += red[gg][d];
        float n2 = tot * tot;
#pragma unroll
        for (int k = 16; k > 0; k >>= 1) n2 += __shfl_xor_sync(0xffffffffu, n2, k);
        float factor = n2 / ((1.f + n2) * sqrtf(n2 + 1e-8f));
        float v = factor * tot;
        g_V[b * OCD + o * OD + d] += v;
        if (is_last) out[((size_t)b * OC + o) * OD + d] = v;
    }
}

extern "C" void kernel_launch(void* const* d_in, const int* in_sizes, int n_in,
                              void* d_out, int out_size) {
    const float* x = (const float*)d_in[0];
    const float* W = (const float*)d_in[1];
    if (n_in >= 2 && in_sizes[0] > in_sizes[1]) {  // defensive: x is the smaller input
        const float* tmp = x; x = W; W = tmp;
    }
    float* out = (float*)d_out;

    init_V<<<(B_ * OCD + 255) / 256, 256>>>();
    uhat_kernel<<<IC, 256>>>(x, W);
    for (int r = 0; r < ITERS; r++) {
        routing_kernel<<<dim3(16, B_), 256>>>();
        update_kernel<<<B_ * OC, 256>>>(out, r == ITERS - 1);
    }
}

// round 5
// speedup vs baseline: 1.7265x; 1.1501x over previous
#include <cuda_runtime.h>
#include <cuda_fp16.h>
#include <math.h>

#define B_    32
#define IC    2048
#define OC    64
#define OD    32
#define ID    16
#define ITERS 5
#define OCD   (OC*OD)   // 2048
#define NSLOT 16        // one partial slot per routing CTA

// Scratch (static device globals; no allocation at launch time).
__device__ __align__(16) __half g_uhat[(size_t)B_ * IC * OCD];   // [b][i][o][d] fp16, 256 MB
__device__ float g_spart[(size_t)B_ * NSLOT * OCD];              // [b][slot][o*32+d] fp32, 4 MB
__device__ float g_V[B_ * OCD];                                  // [b][o*32+d]

__global__ void init_V() {
    int idx = blockIdx.x * blockDim.x + threadIdx.x;
    if (idx < B_ * OCD) g_V[idx] = 0.f;
}

// ---- packed f32x2 helpers (Blackwell FFMA2; ptxas won't emit from C++) ----
__device__ __forceinline__ unsigned long long pk2(float a, float b) {
    unsigned long long r;
    asm("mov.b64 %0, {%1, %2};" : "=l"(r) : "f"(a), "f"(b));
    return r;
}
__device__ __forceinline__ unsigned long long fma2(unsigned long long a,
                                                   unsigned long long b,
                                                   unsigned long long c) {
    unsigned long long r;
    asm("fma.rn.f32x2 %0, %1, %2, %3;" : "=l"(r) : "l"(a), "l"(b), "l"(c));
    return r;
}
__device__ __forceinline__ float2 unpk2(unsigned long long v) {
    float2 f;
    asm("mov.b64 {%0, %1}, %2;" : "=f"(f.x), "=f"(f.y) : "l"(v));
    return f;
}

// Pass A: u_hat[b,i,o,d] = sum_k W[i,o,d,k] * x[b,i,k], fp16 store.
// One CTA per i. Thread owns 4 rows as 2 f32x2 chains: (2t,2t+1) and (+512).
// x prepacked as (x,x) ull in smem; inner loop: 8 LDS.128 + 32 FFMA2 + 2 STG.32.
__global__ __launch_bounds__(256) void uhat_kernel(const float* __restrict__ x,
                                                   const float* __restrict__ W) {
    int i = blockIdx.x;
    int t = threadIdx.x;
    __shared__ __align__(16) unsigned long long xs2[B_][ID];   // (xk, xk)
    for (int idx = t; idx < B_ * ID; idx += 256) {
        int b = idx >> 4, k = idx & 15;
        float xv = x[((size_t)b * IC + i) * ID + k];
        xs2[b][k] = pk2(xv, xv);
    }
    __syncthreads();

#pragma unroll
    for (int j = 0; j < 2; j++) {
        int r0 = 1024 * j + 2 * t;    // chain A rows r0, r0+1
        int r1 = r0 + 512;            // chain B rows r1, r1+1
        const float4* wa0 = (const float4*)(W + ((size_t)i * OCD + r0) * ID);
        const float4* wa1 = (const float4*)(W + ((size_t)i * OCD + r0 + 1) * ID);
        const float4* wb0 = (const float4*)(W + ((size_t)i * OCD + r1) * ID);
        const float4* wb1 = (const float4*)(W + ((size_t)i * OCD + r1 + 1) * ID);

        unsigned long long wpA[ID], wpB[ID];
#pragma unroll
        for (int c = 0; c < 4; c++) {
            float4 a0 = wa0[c], a1 = wa1[c];
            wpA[4 * c + 0] = pk2(a0.x, a1.x);
            wpA[4 * c + 1] = pk2(a0.y, a1.y);
            wpA[4 * c + 2] = pk2(a0.z, a1.z);
            wpA[4 * c + 3] = pk2(a0.w, a1.w);
            float4 b0 = wb0[c], b1 = wb1[c];
            wpB[4 * c + 0] = pk2(b0.x, b1.x);
            wpB[4 * c + 1] = pk2(b0.y, b1.y);
            wpB[4 * c + 2] = pk2(b0.z, b1.z);
            wpB[4 * c + 3] = pk2(b0.w, b1.w);
        }

        for (int b = 0; b < B_; b++) {
            const ulonglong2* xp = (const ulonglong2*)xs2[b];
            unsigned long long accA = 0ull, accB = 0ull;  // bits of (0.f,0.f)
#pragma unroll
            for (int kk = 0; kk < 8; kk++) {
                ulonglong2 xv = xp[kk];
                accA = fma2(wpA[2 * kk],     xv.x, accA);
                accA = fma2(wpA[2 * kk + 1], xv.y, accA);
                accB = fma2(wpB[2 * kk],     xv.x, accB);
                accB = fma2(wpB[2 * kk + 1], xv.y, accB);
            }
            float2 uA = unpk2(accA), uB = unpk2(accB);
            size_t base = ((size_t)b * IC + i) * OCD;
            *(__half2*)(g_uhat + base + r0) = __floats2half2_rn(uA.x, uA.y);
            *(__half2*)(g_uhat + base + r1) = __floats2half2_rn(uB.x, uB.y);
        }
    }
}

// Routing pass. Grid (16 chunks, 32 b), 128 thr (4 warps). Warp w: 32 i's, lane = d.
// Per-CTA smem reduction over 4 warps -> one fp32 slot per CTA.
__global__ __launch_bounds__(128) void routing_kernel() {
    int chunk = blockIdx.x;
    int b = blockIdx.y;
    int t = threadIdx.x;
    int w = t >> 5, d = t & 31;

    __shared__ float Vs[OCD];                // 8 KB
    __shared__ float red[4][OC][OD];         // 32 KB
    for (int idx = t; idx < OCD; idx += 128) Vs[idx] = g_V[b * OCD + idx];
    __syncthreads();

    float acc[OC];
#pragma unroll
    for (int o = 0; o < OC; o++) acc[o] = 0.f;

    for (int ii = 0; ii < 32; ii++) {
        int i = chunk * 128 + ii * 4 + w;
        const __half* up = g_uhat + ((size_t)b * IC + i) * OCD + d;
        float u[OC];
#pragma unroll
        for (int o = 0; o < OC; o++) u[o] = __half2float(up[o * OD]);  // 64B coalesced

        float m = -1e30f;
#pragma unroll
        for (int o = 0; o < OC; o++) m = fmaxf(m, u[o] * Vs[o * OD + d]);

        float Z = 0.f;
#pragma unroll
        for (int o = 0; o < OC; o++) {
            float e = __expf(fmaf(u[o], Vs[o * OD + d], -m));
            Z += e;
            u[o] *= e;
        }
        float rZ = 1.0f / Z;
#pragma unroll
        for (int o = 0; o < OC; o++) acc[o] = fmaf(u[o], rZ, acc[o]);
    }

#pragma unroll
    for (int o = 0; o < OC; o++) red[w][o][d] = acc[o];
    __syncthreads();

    // 2048 outputs / 128 threads = 16 each; lane=d keeps stores coalesced.
#pragma unroll
    for (int r = 0; r < 16; r++) {
        int o = (t >> 5) * 16 + r;
        float s = red[0][o][d] + red[1][o][d] + red[2][o][d] + red[3][o][d];
        g_spart[((size_t)(b * NSLOT + chunk)) * OCD + o * OD + d] = s;
    }
}

// Reduce 16 fp32 slots, squash over d, update V (+ output on last iter).
__global__ __launch_bounds__(128) void update_kernel(float* __restrict__ out, int is_last) {
    int bo = blockIdx.x;       // 0..2047
    int b = bo >> 6, o = bo & 63;
    int t = threadIdx.x;
    int g = t >> 5, d = t & 31;

    float s = 0.f;
#pragma unroll
    for (int k = 0; k < 4; k++)
        s += g_spart[((size_t)(b * NSLOT + g + 4 * k)) * OCD + o * OD + d];

    __shared__ float red[4][OD];
    red[g][d] = s;
    __syncthreads();

    if (t < 32) {
        float tot = red[0][d] + red[1][d] + red[2][d] + red[3][d];
        float n2 = tot * tot;
#pragma unroll
        for (int k = 16; k > 0; k >>= 1) n2 += __shfl_xor_sync(0xffffffffu, n2, k);
        float factor = n2 / ((1.f + n2) * sqrtf(n2 + 1e-8f));
        float v = factor * tot;
        g_V[b * OCD + o * OD + d] += v;
        if (is_last) out[((size_t)b * OC + o) * OD + d] = v;
    }
}

extern "C" void kernel_launch(void* const* d_in, const int* in_sizes, int n_in,
                              void* d_out, int out_size) {
    const float* x = (const float*)d_in[0];
    const float* W = (const float*)d_in[1];
    if (n_in >= 2 && in_sizes[0] > in_sizes[1]) {  // defensive: x is the smaller input
        const float* tmp = x; x = W; W = tmp;
    }
    float* out = (float*)d_out;

    init_V<<<(B_ * OCD + 255) / 256, 256>>>();
    uhat_kernel<<<IC, 256>>>(x, W);
    for (int r = 0; r < ITERS; r++) {
        routing_kernel<<<dim3(NSLOT, B_), 128>>>();
        update_kernel<<<B_ * OC, 128>>>(out, r == ITERS - 1);
    }
}

// round 6
// speedup vs baseline: 1.7533x; 1.0155x over previous
#include <cuda_runtime.h>
#include <cuda_fp16.h>
#include <math.h>

#define B_    32
#define IC    2048
#define OC    64
#define OD    32
#define ID    16
#define ITERS 5
#define OCD   (OC*OD)   // 2048
#define NSLOT 16
#define LOG2E 1.4426950408889634f

// Scratch (static device globals; no allocation at launch time).
// u_hat layout: [b][i][d][o] halves (p = d*64 + o) -> lane d owns a contiguous 128B row.
__device__ __align__(16) __half g_uhat[(size_t)B_ * IC * OCD];   // 256 MB
__device__ float g_spart[(size_t)B_ * NSLOT * OCD];              // [b][slot][o*32+d] fp32, 4 MB
__device__ float g_V[B_ * OCD];                                  // [b][o*32+d]

__global__ void init_V(int off) {
    int idx = off + blockIdx.x * blockDim.x + threadIdx.x;
    if (idx < B_ * OCD) g_V[idx] = 0.f;
}

// ---- packed f32x2 helpers (Blackwell; ptxas won't emit from C++) ----
__device__ __forceinline__ unsigned long long pk2(float a, float b) {
    unsigned long long r;
    asm("mov.b64 %0, {%1, %2};" : "=l"(r) : "f"(a), "f"(b));
    return r;
}
__device__ __forceinline__ unsigned long long fma2(unsigned long long a,
                                                   unsigned long long b,
                                                   unsigned long long c) {
    unsigned long long r;
    asm("fma.rn.f32x2 %0, %1, %2, %3;" : "=l"(r) : "l"(a), "l"(b), "l"(c));
    return r;
}
__device__ __forceinline__ float2 unpk2(unsigned long long v) {
    float2 f;
    asm("mov.b64 {%0, %1}, %2;" : "=f"(f.x), "=f"(f.y) : "l"(v));
    return f;
}

// Pass A: u_hat[b,i,d,o] = sum_k W[i,o,d,k] * x[b,i,k], fp16 store, layout [d][o].
// CTA per i. j=0..3: warp w owns d = 8j+w; lane l owns o-pair (2l, 2l+1).
// W rows o*32+d (strided across lanes; L2-friendly within CTA); stores half2 coalesced.
__global__ __launch_bounds__(256) void uhat_kernel(const float* __restrict__ x,
                                                   const float* __restrict__ W) {
    int i = blockIdx.x;
    int t = threadIdx.x;
    int w = t >> 5, l = t & 31;
    __shared__ __align__(16) unsigned long long xs2[B_][ID];   // (xk, xk)
    for (int idx = t; idx < B_ * ID; idx += 256) {
        int b = idx >> 4, k = idx & 15;
        float xv = x[((size_t)b * IC + i) * ID + k];
        xs2[b][k] = pk2(xv, xv);
    }
    __syncthreads();

#pragma unroll
    for (int j = 0; j < 4; j++) {
        int d = 8 * j + w;
        int o0 = 2 * l;
        const float4* w0p = (const float4*)(W + ((size_t)i * OCD + (size_t)o0 * OD + d) * ID);
        const float4* w1p = (const float4*)(W + ((size_t)i * OCD + (size_t)(o0 + 1) * OD + d) * ID);

        unsigned long long wp[ID];
#pragma unroll
        for (int c = 0; c < 4; c++) {
            float4 a = w0p[c], bb = w1p[c];
            wp[4 * c + 0] = pk2(a.x, bb.x);
            wp[4 * c + 1] = pk2(a.y, bb.y);
            wp[4 * c + 2] = pk2(a.z, bb.z);
            wp[4 * c + 3] = pk2(a.w, bb.w);
        }

        for (int b = 0; b < B_; b++) {
            const ulonglong2* xp = (const ulonglong2*)xs2[b];
            unsigned long long acc = 0ull;  // (0.f, 0.f)
#pragma unroll
            for (int kk = 0; kk < 8; kk++) {
                ulonglong2 xv = xp[kk];
                acc = fma2(wp[2 * kk],     xv.x, acc);
                acc = fma2(wp[2 * kk + 1], xv.y, acc);
            }
            float2 u = unpk2(acc);
            size_t base = ((size_t)b * IC + i) * OCD;
            *(__half2*)(g_uhat + base + (size_t)d * OC + o0) = __floats2half2_rn(u.x, u.y);
        }
    }
}

// Routing pass. Grid (16, 32), 128 thr (4 warps). Warp w: 32 i's, lane = d.
// Per i: 8 LDG.128 -> 32 half2 over o-pairs; half2 max pass; fp32 exp/Z/acc.
__global__ __launch_bounds__(128) void routing_kernel() {
    int chunk = blockIdx.x;
    int b = blockIdx.y;
    int t = threadIdx.x;
    int w = t >> 5, d = t & 31;

    __shared__ float2 Vsf[32][32];       // [q][d], pre-scaled by log2(e); 8 KB
    __shared__ float red[4][OC][OD];     // 32 KB
    for (int idx = t; idx < 1024; idx += 128) {
        int q = idx >> 5, dd = idx & 31;
        float v0 = g_V[b * OCD + (2 * q) * OD + dd] * LOG2E;
        float v1 = g_V[b * OCD + (2 * q + 1) * OD + dd] * LOG2E;
        Vsf[q][dd] = make_float2(v0, v1);
    }
    __syncthreads();

    // per-thread half2 V (scaled) in registers
    unsigned int Vh[32];
#pragma unroll
    for (int q = 0; q < 32; q++) {
        float2 vv = Vsf[q][d];
        __half2 h = __floats2half2_rn(vv.x, vv.y);
        Vh[q] = *(unsigned int*)&h;
    }

    float acc[OC];
#pragma unroll
    for (int o = 0; o < OC; o++) acc[o] = 0.f;

    for (int ii = 0; ii < 32; ii++) {
        int i = chunk * 128 + ii * 4 + w;
        const uint4* up = (const uint4*)(g_uhat + ((size_t)b * IC + i) * OCD + (size_t)d * OC);
        unsigned int U[32];
#pragma unroll
        for (int k = 0; k < 8; k++) {
            uint4 r = up[k];
            U[4 * k + 0] = r.x; U[4 * k + 1] = r.y;
            U[4 * k + 2] = r.z; U[4 * k + 3] = r.w;
        }

        // max pass in half2 (approximate m is exactly softmax-safe)
        __half2 mh = __float2half2_rn(-60000.f);
#pragma unroll
        for (int q = 0; q < 32; q++)
            mh = __hmax2(mh, __hmul2(*(__half2*)&U[q], *(__half2*)&Vh[q]));
        float2 mf = __half22float2(mh);
        float m = fmaxf(mf.x, mf.y);

        // exp pass (fp32, exp2 with pre-scaled V); stash e*u back into U
        float Z = 0.f;
#pragma unroll
        for (int q = 0; q < 32; q++) {
            float2 uf = __half22float2(*(__half2*)&U[q]);
            float2 vf = Vsf[q][d];
            float e0 = exp2f(fmaf(uf.x, vf.x, -m));
            float e1 = exp2f(fmaf(uf.y, vf.y, -m));
            Z += e0 + e1;
            __half2 th = __floats2half2_rn(uf.x * e0, uf.y * e1);
            U[q] = *(unsigned int*)&th;
        }
        float rZ = __fdividef(1.0f, Z);
#pragma unroll
        for (int q = 0; q < 32; q++) {
            float2 tf = __half22float2(*(__half2*)&U[q]);
            acc[2 * q]     = fmaf(tf.x, rZ, acc[2 * q]);
            acc[2 * q + 1] = fmaf(tf.y, rZ, acc[2 * q + 1]);
        }
    }

#pragma unroll
    for (int o = 0; o < OC; o++) red[w][o][d] = acc[o];
    __syncthreads();

#pragma unroll
    for (int r = 0; r < 16; r++) {
        int o = w * 16 + r;
        float s = red[0][o][d] + red[1][o][d] + red[2][o][d] + red[3][o][d];
        g_spart[((size_t)(b * NSLOT + chunk)) * OCD + o * OD + d] = s;
    }
}

// Reduce 16 fp32 slots, squash over d, update V (+ output on last iter).
__global__ __launch_bounds__(128) void update_kernel(float* __restrict__ out, int is_last) {
    int bo = blockIdx.x;       // 0..2047
    int b = bo >> 6, o = bo & 63;
    int t = threadIdx.x;
    int g = t >> 5, d = t & 31;

    float s = 0.f;
#pragma unroll
    for (int k = 0; k < 4; k++)
        s += g_spart[((size_t)(b * NSLOT + g + 4 * k)) * OCD + o * OD + d];

    __shared__ float red[4][OD];
    red[g][d] = s;
    __syncthreads();

    if (t < 32) {
        float tot = red[0][d] + red[1][d] + red[2][d] + red[3][d];
        float n2 = tot * tot;
#pragma unroll
        for (int k = 16; k > 0; k >>= 1) n2 += __shfl_xor_sync(0xffffffffu, n2, k);
        float factor = n2 / ((1.f + n2) * sqrtf(n2 + 1e-8f));
        float v = factor * tot;
        g_V[b * OCD + o * OD + d] += v;
        if (is_last) out[((size_t)b * OC + o) * OD + d] = v;
    }
}

extern "C" void kernel_launch(void* const* d_in, const int* in_sizes, int n_in,
                              void* d_out, int out_size) {
    const float* x = (const float*)d_in[0];
    const float* W = (const float*)d_in[1];
    if (n_in >= 2 && in_sizes[0] > in_sizes[1]) {  // defensive: x is the smaller input
        const float* tmp = x; x = W; W = tmp;
    }
    float* out = (float*)d_out;

    // two init launches (also aligns ncu -s 5 onto routing_kernel)
    init_V<<<128, 256>>>(0);
    init_V<<<128, 256>>>(32768);
    uhat_kernel<<<IC, 256>>>(x, W);
    for (int r = 0; r < ITERS; r++) {
        routing_kernel<<<dim3(NSLOT, B_), 128>>>();
        update_kernel<<<B_ * OC, 128>>>(out, r == ITERS - 1);
    }
}

// round 7
// speedup vs baseline: 2.0860x; 1.1898x over previous
#include <cuda_runtime.h>
#include <cuda_fp16.h>
#include <math.h>

#define B_    32
#define IC    2048
#define OC    64
#define OD    32
#define ID    16
#define ITERS 5
#define OCD   (OC*OD)   // 2048
#define NSLOT 16
#define LOG2E 1.4426950408889634f

// Scratch (static device globals; no allocation at launch time).
// u_hat layout: [b][i][d][o] halves (p = d*64 + o).
__device__ __align__(16) __half g_uhat[(size_t)B_ * IC * OCD];   // 256 MB
__device__ float g_spart[(size_t)B_ * NSLOT * OCD];              // [b][slot][o*32+d] fp32, 4 MB
__device__ float g_V[B_ * OCD];                                  // [b][o*32+d]

__global__ void init_V(int off) {
    int idx = off + blockIdx.x * blockDim.x + threadIdx.x;
    if (idx < B_ * OCD) g_V[idx] = 0.f;
}

// ---- packed f32x2 helpers (Blackwell; ptxas won't emit from C++) ----
__device__ __forceinline__ unsigned long long pk2(float a, float b) {
    unsigned long long r;
    asm("mov.b64 %0, {%1, %2};" : "=l"(r) : "f"(a), "f"(b));
    return r;
}
__device__ __forceinline__ unsigned long long fma2(unsigned long long a,
                                                   unsigned long long b,
                                                   unsigned long long c) {
    unsigned long long r;
    asm("fma.rn.f32x2 %0, %1, %2, %3;" : "=l"(r) : "l"(a), "l"(b), "l"(c));
    return r;
}
__device__ __forceinline__ float2 unpk2(unsigned long long v) {
    float2 f;
    asm("mov.b64 {%0, %1}, %2;" : "=f"(f.x), "=f"(f.y) : "l"(v));
    return f;
}

// Pass A: u_hat[b,i,d,o] = sum_k W[i,o,d,k] * x[b,i,k], fp16 store, layout [d][o].
__global__ __launch_bounds__(256) void uhat_kernel(const float* __restrict__ x,
                                                   const float* __restrict__ W) {
    int i = blockIdx.x;
    int t = threadIdx.x;
    int w = t >> 5, l = t & 31;
    __shared__ __align__(16) unsigned long long xs2[B_][ID];   // (xk, xk)
    for (int idx = t; idx < B_ * ID; idx += 256) {
        int b = idx >> 4, k = idx & 15;
        float xv = x[((size_t)b * IC + i) * ID + k];
        xs2[b][k] = pk2(xv, xv);
    }
    __syncthreads();

#pragma unroll
    for (int j = 0; j < 4; j++) {
        int d = 8 * j + w;
        int o0 = 2 * l;
        const float4* w0p = (const float4*)(W + ((size_t)i * OCD + (size_t)o0 * OD + d) * ID);
        const float4* w1p = (const float4*)(W + ((size_t)i * OCD + (size_t)(o0 + 1) * OD + d) * ID);

        unsigned long long wp[ID];
#pragma unroll
        for (int c = 0; c < 4; c++) {
            float4 a = w0p[c], bb = w1p[c];
            wp[4 * c + 0] = pk2(a.x, bb.x);
            wp[4 * c + 1] = pk2(a.y, bb.y);
            wp[4 * c + 2] = pk2(a.z, bb.z);
            wp[4 * c + 3] = pk2(a.w, bb.w);
        }

        for (int b = 0; b < B_; b++) {
            const ulonglong2* xp = (const ulonglong2*)xs2[b];
            unsigned long long acc = 0ull;
#pragma unroll
            for (int kk = 0; kk < 8; kk++) {
                ulonglong2 xv = xp[kk];
                acc = fma2(wp[2 * kk],     xv.x, acc);
                acc = fma2(wp[2 * kk + 1], xv.y, acc);
            }
            float2 u = unpk2(acc);
            size_t base = ((size_t)b * IC + i) * OCD;
            *(__half2*)(g_uhat + base + (size_t)d * OC + o0) = __floats2half2_rn(u.x, u.y);
        }
    }
}

// Routing pass v3 — low register pressure, 4 CTAs/SM.
// Grid (16 chunks, 32 b), 128 thr (4 warps).
// Warp w: iset = w>>1 (64 i's each), dhalf = w&1. Lane l: d16 = l>>1, oh = l&1;
// d = dhalf*16 + d16. Thread covers o in [32*oh, 32*oh+32) -> U[16] half2, acc[32].
// Softmax m/Z combined across the o-halves via shfl_xor(1) (lane pairs share d).
__global__ __launch_bounds__(128, 4) void routing_kernel() {
    int chunk = blockIdx.x;
    int b = blockIdx.y;
    int t = threadIdx.x;
    int w = t >> 5, l = t & 31;
    int iset = w >> 1, dhalf = w & 1;
    int d = dhalf * 16 + (l >> 1);
    int oh = l & 1;

    __shared__ float2 Vsf[32][32];           // [opair][d], scaled by log2e; 8 KB
    __shared__ float red[2][OC][OD];         // [iset][o][d]; 16 KB
    for (int idx = t; idx < 1024; idx += 128) {
        int q = idx >> 5, dd = idx & 31;
        float v0 = g_V[b * OCD + (2 * q) * OD + dd] * LOG2E;
        float v1 = g_V[b * OCD + (2 * q + 1) * OD + dd] * LOG2E;
        Vsf[q][dd] = make_float2(v0, v1);
    }
    __syncthreads();

    unsigned int Vh[16];
#pragma unroll
    for (int q = 0; q < 16; q++) {
        float2 vv = Vsf[oh * 16 + q][d];
        __half2 h = __floats2half2_rn(vv.x, vv.y);
        Vh[q] = *(unsigned int*)&h;
    }

    float acc[32];
#pragma unroll
    for (int j = 0; j < 32; j++) acc[j] = 0.f;

    for (int ii = 0; ii < 64; ii++) {
        int i = chunk * 128 + iset * 64 + ii;
        // lane offset: d*64 + oh*32 halves; warp covers contiguous 2KB
        const uint4* up = (const uint4*)(g_uhat + ((size_t)b * IC + i) * OCD
                                         + (size_t)d * OC + oh * 32);
        unsigned int U[16];
#pragma unroll
        for (int k = 0; k < 4; k++) {
            uint4 r = up[k];
            U[4 * k + 0] = r.x; U[4 * k + 1] = r.y;
            U[4 * k + 2] = r.z; U[4 * k + 3] = r.w;
        }

        // local max (half2), then combine across o-halves (lane pair)
        __half2 mh = __float2half2_rn(-60000.f);
#pragma unroll
        for (int q = 0; q < 16; q++)
            mh = __hmax2(mh, __hmul2(*(__half2*)&U[q], *(__half2*)&Vh[q]));
        float2 mf = __half22float2(mh);
        float m = fmaxf(mf.x, mf.y);
        m = fmaxf(m, __shfl_xor_sync(0xffffffffu, m, 1));

        // exp pass (fp32 logits, exp2 with pre-scaled V); stash e*u into U
        float Z = 0.f;
#pragma unroll
        for (int q = 0; q < 16; q++) {
            float2 uf = __half22float2(*(__half2*)&U[q]);
            float2 vf = Vsf[oh * 16 + q][d];
            float e0 = exp2f(fmaf(uf.x, vf.x, -m));
            float e1 = exp2f(fmaf(uf.y, vf.y, -m));
            Z += e0 + e1;
            __half2 th = __floats2half2_rn(uf.x * e0, uf.y * e1);
            U[q] = *(unsigned int*)&th;
        }
        Z += __shfl_xor_sync(0xffffffffu, Z, 1);
        float rZ = __fdividef(1.0f, Z);
#pragma unroll
        for (int q = 0; q < 16; q++) {
            float2 tf = __half22float2(*(__half2*)&U[q]);
            acc[2 * q]     = fmaf(tf.x, rZ, acc[2 * q]);
            acc[2 * q + 1] = fmaf(tf.y, rZ, acc[2 * q + 1]);
        }
    }

#pragma unroll
    for (int j = 0; j < 32; j++) red[iset][oh * 32 + j][d] = acc[j];
    __syncthreads();

    // 2048 outputs / 128 threads = 16 each; lane = d keeps stores coalesced.
#pragma unroll
    for (int r = 0; r < 16; r++) {
        int o = w * 16 + r;
        float s = red[0][o][l] + red[1][o][l];
        g_spart[((size_t)(b * NSLOT + chunk)) * OCD + o * OD + l] = s;
    }
}

// Reduce 16 fp32 slots, squash over d, update V (+ output on last iter).
__global__ __launch_bounds__(128) void update_kernel(float* __restrict__ out, int is_last) {
    int bo = blockIdx.x;       // 0..2047
    int b = bo >> 6, o = bo & 63;
    int t = threadIdx.x;
    int g = t >> 5, d = t & 31;

    float s = 0.f;
#pragma unroll
    for (int k = 0; k < 4; k++)
        s += g_spart[((size_t)(b * NSLOT + g + 4 * k)) * OCD + o * OD + d];

    __shared__ float red[4][OD];
    red[g][d] = s;
    __syncthreads();

    if (t < 32) {
        float tot = red[0][d] + red[1][d] + red[2][d] + red[3][d];
        float n2 = tot * tot;
#pragma unroll
        for (int k = 16; k > 0; k >>= 1) n2 += __shfl_xor_sync(0xffffffffu, n2, k);
        float factor = n2 / ((1.f + n2) * sqrtf(n2 + 1e-8f));
        float v = factor * tot;
        g_V[b * OCD + o * OD + d] += v;
        if (is_last) out[((size_t)b * OC + o) * OD + d] = v;
    }
}

extern "C" void kernel_launch(void* const* d_in, const int* in_sizes, int n_in,
                              void* d_out, int out_size) {
    const float* x = (const float*)d_in[0];
    const float* W = (const float*)d_in[1];
    if (n_in >= 2 && in_sizes[0] > in_sizes[1]) {  // defensive: x is the smaller input
        const float* tmp = x; x = W; W = tmp;
    }
    float* out = (float*)d_out;

    init_V<<<128, 256>>>(0);
    init_V<<<128, 256>>>(32768);
    uhat_kernel<<<IC, 256>>>(x, W);
    for (int r = 0; r < ITERS; r++) {
        routing_kernel<<<dim3(NSLOT, B_), 128>>>();
        update_kernel<<<B_ * OC, 128>>>(out, r == ITERS - 1);
    }
}

// round 8
// speedup vs baseline: 2.2010x; 1.0551x over previous
#include <cuda_runtime.h>
#include <cuda_fp16.h>
#include <math.h>

#define B_    32
#define IC    2048
#define OC    64
#define OD    32
#define ID    16
#define ITERS 5
#define OCD   (OC*OD)   // 2048
#define NSLOT 32
#define LOG2E 1.4426950408889634f

// Scratch (static device globals; no allocation at launch time).
// u_hat layout: [b][i][d][o] halves (p = d*64 + o).
__device__ __align__(16) __half g_uhat[(size_t)B_ * IC * OCD];   // 256 MB
__device__ float g_spart[(size_t)B_ * NSLOT * OCD];              // [b][slot][o*32+d] fp32, 8 MB
__device__ float g_V[B_ * OCD];                                  // [b][o*32+d]

__global__ void init_V(int off) {
    int idx = off + blockIdx.x * blockDim.x + threadIdx.x;
    if (idx < B_ * OCD) g_V[idx] = 0.f;
}

// ---- packed f32x2 helpers (Blackwell; ptxas won't emit from C++) ----
__device__ __forceinline__ unsigned long long pk2(float a, float b) {
    unsigned long long r;
    asm("mov.b64 %0, {%1, %2};" : "=l"(r) : "f"(a), "f"(b));
    return r;
}
__device__ __forceinline__ unsigned long long fma2(unsigned long long a,
                                                   unsigned long long b,
                                                   unsigned long long c) {
    unsigned long long r;
    asm("fma.rn.f32x2 %0, %1, %2, %3;" : "=l"(r) : "l"(a), "l"(b), "l"(c));
    return r;
}
__device__ __forceinline__ float2 unpk2(unsigned long long v) {
    float2 f;
    asm("mov.b64 {%0, %1}, %2;" : "=f"(f.x), "=f"(f.y) : "l"(v));
    return f;
}

// Pass A: u_hat[b,i,d,o] = sum_k W[i,o,d,k] * x[b,i,k], fp16 store, layout [d][o].
__global__ __launch_bounds__(256) void uhat_kernel(const float* __restrict__ x,
                                                   const float* __restrict__ W) {
    int i = blockIdx.x;
    int t = threadIdx.x;
    int w = t >> 5, l = t & 31;
    __shared__ __align__(16) unsigned long long xs2[B_][ID];   // (xk, xk)
    for (int idx = t; idx < B_ * ID; idx += 256) {
        int b = idx >> 4, k = idx & 15;
        float xv = x[((size_t)b * IC + i) * ID + k];
        xs2[b][k] = pk2(xv, xv);
    }
    __syncthreads();

#pragma unroll
    for (int j = 0; j < 4; j++) {
        int d = 8 * j + w;
        int o0 = 2 * l;
        const float4* w0p = (const float4*)(W + ((size_t)i * OCD + (size_t)o0 * OD + d) * ID);
        const float4* w1p = (const float4*)(W + ((size_t)i * OCD + (size_t)(o0 + 1) * OD + d) * ID);

        unsigned long long wp[ID];
#pragma unroll
        for (int c = 0; c < 4; c++) {
            float4 a = w0p[c], bb = w1p[c];
            wp[4 * c + 0] = pk2(a.x, bb.x);
            wp[4 * c + 1] = pk2(a.y, bb.y);
            wp[4 * c + 2] = pk2(a.z, bb.z);
            wp[4 * c + 3] = pk2(a.w, bb.w);
        }

        for (int b = 0; b < B_; b++) {
            const ulonglong2* xp = (const ulonglong2*)xs2[b];
            unsigned long long acc = 0ull;
#pragma unroll
            for (int kk = 0; kk < 8; kk++) {
                ulonglong2 xv = xp[kk];
                acc = fma2(wp[2 * kk],     xv.x, acc);
                acc = fma2(wp[2 * kk + 1], xv.y, acc);
            }
            float2 u = unpk2(acc);
            size_t base = ((size_t)b * IC + i) * OCD;
            *(__half2*)(g_uhat + base + (size_t)d * OC + o0) = __floats2half2_rn(u.x, u.y);
        }
    }
}

// Routing pass v4 — ~60 regs/thread, 8 CTAs/SM.
// Grid (32 chunks, 32 b), 128 thr (4 warps). Chunk = 64 i's.
// Warp w owns d-range [8w, 8w+8); lane l: d8 = l>>2, oq = l&3; d = 8w + d8.
// Thread covers o in [16*oq, 16*oq+16) for ALL 64 i's -> no cross-warp reduce.
// Softmax m/Z combined over the 4 o-quarters via shfl_xor(1), shfl_xor(2).
__global__ __launch_bounds__(128, 8) void routing_kernel() {
    int chunk = blockIdx.x;
    int b = blockIdx.y;
    int t = threadIdx.x;
    int w = t >> 5, l = t & 31;
    int d8 = l >> 2, oq = l & 3;
    int d = w * 8 + d8;

    __shared__ float2 Vsf[32][32];   // [opair][d], scaled by log2e; 8 KB
    __shared__ float red[OC][OD];    // staging for coalesced spart store; 8 KB
    for (int idx = t; idx < 1024; idx += 128) {
        int q = idx >> 5, dd = idx & 31;
        float v0 = g_V[b * OCD + (2 * q) * OD + dd] * LOG2E;
        float v1 = g_V[b * OCD + (2 * q + 1) * OD + dd] * LOG2E;
        Vsf[q][dd] = make_float2(v0, v1);
    }
    __syncthreads();

    unsigned int Vh[8];
#pragma unroll
    for (int q = 0; q < 8; q++) {
        float2 vv = Vsf[oq * 8 + q][d];
        __half2 h = __floats2half2_rn(vv.x, vv.y);
        Vh[q] = *(unsigned int*)&h;
    }

    float acc[16];
#pragma unroll
    for (int j = 0; j < 16; j++) acc[j] = 0.f;

    for (int ii = 0; ii < 64; ii++) {
        int i = chunk * 64 + ii;
        // lane offset d*64 + oq*16 halves; warp covers contiguous 1KB
        const uint4* up = (const uint4*)(g_uhat + ((size_t)b * IC + i) * OCD
                                         + (size_t)d * OC + oq * 16);
        uint4 r0 = up[0], r1 = up[1];
        unsigned int U[8] = {r0.x, r0.y, r0.z, r0.w, r1.x, r1.y, r1.z, r1.w};

        // local max (half2), then combine across 4 o-quarters (lanes xor 1, 2)
        __half2 mh = __float2half2_rn(-60000.f);
#pragma unroll
        for (int q = 0; q < 8; q++)
            mh = __hmax2(mh, __hmul2(*(__half2*)&U[q], *(__half2*)&Vh[q]));
        float2 mf = __half22float2(mh);
        float m = fmaxf(mf.x, mf.y);
        m = fmaxf(m, __shfl_xor_sync(0xffffffffu, m, 1));
        m = fmaxf(m, __shfl_xor_sync(0xffffffffu, m, 2));

        // exp pass (fp32 logits, exp2 with pre-scaled V); stash e*u into U
        float Z = 0.f;
#pragma unroll
        for (int q = 0; q < 8; q++) {
            float2 uf = __half22float2(*(__half2*)&U[q]);
            float2 vf = Vsf[oq * 8 + q][d];
            float e0 = exp2f(fmaf(uf.x, vf.x, -m));
            float e1 = exp2f(fmaf(uf.y, vf.y, -m));
            Z += e0 + e1;
            __half2 th = __floats2half2_rn(uf.x * e0, uf.y * e1);
            U[q] = *(unsigned int*)&th;
        }
        Z += __shfl_xor_sync(0xffffffffu, Z, 1);
        Z += __shfl_xor_sync(0xffffffffu, Z, 2);
        float rZ = __fdividef(1.0f, Z);
#pragma unroll
        for (int q = 0; q < 8; q++) {
            float2 tf = __half22float2(*(__half2*)&U[q]);
            acc[2 * q]     = fmaf(tf.x, rZ, acc[2 * q]);
            acc[2 * q + 1] = fmaf(tf.y, rZ, acc[2 * q + 1]);
        }
    }

#pragma unroll
    for (int j = 0; j < 16; j++) red[oq * 16 + j][d] = acc[j];
    __syncthreads();

    // coalesced store: 2048 floats, lanes consecutive
    float* sp = g_spart + ((size_t)(b * NSLOT + chunk)) * OCD;
#pragma unroll
    for (int r = 0; r < 16; r++) {
        int p = t + 128 * r;
        sp[p] = ((const float*)red)[p];
    }
}

// Reduce 32 fp32 slots, squash over d, update V (+ output on last iter).
__global__ __launch_bounds__(128) void update_kernel(float* __restrict__ out, int is_last) {
    int bo = blockIdx.x;       // 0..2047
    int b = bo >> 6, o = bo & 63;
    int t = threadIdx.x;
    int g = t >> 5, d = t & 31;

    float s = 0.f;
#pragma unroll
    for (int k = 0; k < 8; k++)
        s += g_spart[((size_t)(b * NSLOT + g + 4 * k)) * OCD + o * OD + d];

    __shared__ float red[4][OD];
    red[g][d] = s;
    __syncthreads();

    if (t < 32) {
        float tot = red[0][d] + red[1][d] + red[2][d] + red[3][d];
        float n2 = tot * tot;
#pragma unroll
        for (int k = 16; k > 0; k >>= 1) n2 += __shfl_xor_sync(0xffffffffu, n2, k);
        float factor = n2 / ((1.f + n2) * sqrtf(n2 + 1e-8f));
        float v = factor * tot;
        g_V[b * OCD + o * OD + d] += v;
        if (is_last) out[((size_t)b * OC + o) * OD + d] = v;
    }
}

extern "C" void kernel_launch(void* const* d_in, const int* in_sizes, int n_in,
                              void* d_out, int out_size) {
    const float* x = (const float*)d_in[0];
    const float* W = (const float*)d_in[1];
    if (n_in >= 2 && in_sizes[0] > in_sizes[1]) {  // defensive: x is the smaller input
        const float* tmp = x; x = W; W = tmp;
    }
    float* out = (float*)d_out;

    init_V<<<128, 256>>>(0);
    init_V<<<128, 256>>>(32768);
    uhat_kernel<<<IC, 256>>>(x, W);
    for (int r = 0; r < ITERS; r++) {
        routing_kernel<<<dim3(NSLOT, B_), 128>>>();
        update_kernel<<<B_ * OC, 128>>>(out, r == ITERS - 1);
    }
}